// round 15
// baseline (speedup 1.0000x reference)
#include <cuda_runtime.h>
#include <cuda_pipeline.h>

#define H 1024
#define B 8
#define T 4096
#define NROWS (B * T)

#define GRID      296              // 148 SMs x 2 blocks — all co-resident
#define NWARPS    (GRID * 8)       // 2368 warps, 13-14 rows each
#define V_WRITERS 256              // blocks 0..255 compute 4 v-rows each
#define STAGES    3
#define SMEM_DYN  (8 * STAGES * H * 4)   // 96 KB: per-warp 3-stage rings

__device__ float g_v[B * H];
__device__ int   g_cnt;            // writer blocks done (self-resetting)
__device__ int   g_passed;         // blocks past spin (self-resetting)

__device__ __forceinline__ int ld_acquire(const int* p) {
    int v;
    asm volatile("ld.global.acquire.gpu.b32 %0, [%1];" : "=r"(v) : "l"(p) : "memory");
    return v;
}

__global__ void __launch_bounds__(256) fused_kernel(
    const float* __restrict__ states,  // (B, T, H)
    const float* __restrict__ ctx,     // (B, H)
    const float* __restrict__ W,       // (H, H)
    const float* __restrict__ bias,    // (1,)
    float* __restrict__ out)           // (B*T,)
{
    extern __shared__ float smem[];    // [8 warps][STAGES][H]
    __shared__ float red[4][8][9];     // v-phase cross-warp reduce

    const int tid  = threadIdx.x;
    const int lane = tid & 31;
    const int warp = tid >> 5;
    const int wg   = blockIdx.x * 8 + warp;

    // ── v-phase: blocks 0..255 compute 4 rows of v = W @ ctx ──
    if (blockIdx.x < V_WRITERS) {
        // Front-batch the 4 W row-slices (DRAM, parallel)
        float4 w4[4];
#pragma unroll
        for (int r = 0; r < 4; r++)
            w4[r] = __ldg(reinterpret_cast<const float4*>(
                        W + (size_t)(blockIdx.x * 4 + r) * H) + tid);

        // Each ctx slice loaded ONCE, feeds all 4 rows
        float acc[4][B];
#pragma unroll
        for (int b = 0; b < B; b++) {
            const float4 c = __ldg(reinterpret_cast<const float4*>(ctx + b * H) + tid);
#pragma unroll
            for (int r = 0; r < 4; r++)
                acc[r][b] = w4[r].x * c.x + w4[r].y * c.y + w4[r].z * c.z + w4[r].w * c.w;
        }
#pragma unroll
        for (int r = 0; r < 4; r++)
#pragma unroll
            for (int b = 0; b < B; b++) {
#pragma unroll
                for (int o = 16; o; o >>= 1)
                    acc[r][b] += __shfl_xor_sync(0xFFFFFFFFu, acc[r][b], o);
            }
        if (lane == 0) {
#pragma unroll
            for (int r = 0; r < 4; r++)
#pragma unroll
                for (int b = 0; b < B; b++) red[r][warp][b] = acc[r][b];
        }
        __syncthreads();
        if (tid < 4 * B) {
            const int r = tid >> 3, b = tid & 7;
            float s = 0.0f;
#pragma unroll
            for (int wi = 0; wi < 8; wi++) s += red[r][wi][b];
            g_v[b * H + blockIdx.x * 4 + r] = s;
        }
        __syncthreads();
        if (tid == 0) {
            __threadfence();
            atomicAdd(&g_cnt, 1);
        }
    }

    // ── spin barrier: all 256 writer blocks done; self-reset for replay ──
    if (tid == 0) {
        while (ld_acquire(&g_cnt) < V_WRITERS) __nanosleep(32);
        const int old = atomicAdd(&g_passed, 1);
        if (old == GRID - 1) {
            atomicExch(&g_cnt, 0);
            atomicExch(&g_passed, 0);
        }
    }
    __syncthreads();

    // ── engine: per-warp 3-stage cp.async ring, no block sync ──
    const float bb = bias[0];
    float* ring = smem + warp * (STAGES * H);

    // Prologue: issue up to 3 rows; commit a group every stage regardless
#pragma unroll
    for (int s = 0; s < STAGES; s++) {
        const int row = wg + s * NWARPS;
        if (row < NROWS) {
            float4* dst = reinterpret_cast<float4*>(ring + s * H);
            const float4* src = reinterpret_cast<const float4*>(states + (size_t)row * H);
#pragma unroll
            for (int k = 0; k < 8; k++)
                __pipeline_memcpy_async(dst + lane + 32 * k, src + lane + 32 * k, 16);
        }
        __pipeline_commit();
    }

    int stage = 0;
    for (int row = wg; row < NROWS; row += NWARPS) {
        __pipeline_wait_prior(STAGES - 1);   // oldest group (this stage) done

        const float4* cur = reinterpret_cast<const float4*>(ring + stage * H);
        const float4* v4  = reinterpret_cast<const float4*>(g_v + ((row >> 12) << 10));

        float acc0 = 0.0f, acc1 = 0.0f;
#pragma unroll
        for (int k = 0; k < 8; k += 2) {
            const float4 x0 = cur[lane + 32 * k];
            const float4 x1 = cur[lane + 32 * (k + 1)];
            const float4 w0 = __ldg(v4 + lane + 32 * k);
            const float4 w1 = __ldg(v4 + lane + 32 * (k + 1));
            acc0 += x0.x * w0.x + x0.y * w0.y + x0.z * w0.z + x0.w * w0.w;
            acc1 += x1.x * w1.x + x1.y * w1.y + x1.z * w1.z + x1.w * w1.w;
        }
        float acc = acc0 + acc1;
#pragma unroll
        for (int o = 16; o; o >>= 1)
            acc += __shfl_xor_sync(0xFFFFFFFFu, acc, o);
        if (lane == 0) out[row] = acc + bb;

        // Refill this stage with the row 3 strides ahead; commit every iter
        const int nr = row + STAGES * NWARPS;
        if (nr < NROWS) {
            float4* dst = reinterpret_cast<float4*>(ring + stage * H);
            const float4* src = reinterpret_cast<const float4*>(states + (size_t)nr * H);
#pragma unroll
            for (int k = 0; k < 8; k++)
                __pipeline_memcpy_async(dst + lane + 32 * k, src + lane + 32 * k, 16);
        }
        __pipeline_commit();

        if (++stage == STAGES) stage = 0;
    }
}

extern "C" void kernel_launch(void* const* d_in, const int* in_sizes, int n_in,
                              void* d_out, int out_size)
{
    const float* states = (const float*)d_in[0];   // (B, T, H)
    const float* ctx    = (const float*)d_in[1];   // (B, H)
    const float* W      = (const float*)d_in[2];   // (1, H, H)
    const float* bias   = (const float*)d_in[3];   // (1,)

    cudaFuncSetAttribute(fused_kernel,
                         cudaFuncAttributeMaxDynamicSharedMemorySize, SMEM_DYN);
    fused_kernel<<<GRID, 256, SMEM_DYN>>>(states, ctx, W, bias, (float*)d_out);
}